// round 16
// baseline (speedup 1.0000x reference)
#include <cuda_runtime.h>
#include <cuda_bf16.h>
#include <cuda_fp16.h>
#include <cstdint>
#include <math.h>

#define DIMC 512
#define NHD  8
#define HDD  64
#define BB   8
#define NN   1024
#define MTOT (BB*NN)   // 8192
#define QKV  (BB*NHD*NN*HDD)

// ---------------- scratch (allocation-free) ----------------
__device__ __align__(16) __half gxh[MTOT*DIMC];        // x   fp16
__device__ __align__(16) __half gwqh[3*DIMC*DIMC];     // w_qkv fp16
__device__ __align__(16) __half gwph[DIMC*DIMC];       // w_proj fp16
__device__ __align__(16) __half gqh[QKV];              // [bh][n][d]
__device__ __align__(16) __half gkh[QKV];              // [bh][n][d]
__device__ __align__(16) __half gvth[QKV];             // [bh][d][n] (transposed)
__device__ __align__(16) __half goh[MTOT*DIMC];        // attn out [b][n][c]

// ---------------- fused fp32 -> fp16 convert (one launch) ----------------
#define CVT_N0 (MTOT*DIMC)
#define CVT_N1 (3*DIMC*DIMC)
#define CVT_N2 (DIMC*DIMC)
#define CVT_TOT (CVT_N0 + CVT_N1 + CVT_N2)

__global__ void cvtall_k(const float* __restrict__ x,
                         const float* __restrict__ wq,
                         const float* __restrict__ wp)
{
    int i = (blockIdx.x * blockDim.x + threadIdx.x) * 4;
    if (i >= CVT_TOT) return;
    const float* s;
    __half* dst;
    int off;
    if (i < CVT_N0)                { s = x;  dst = gxh;  off = i; }
    else if (i < CVT_N0 + CVT_N1)  { s = wq; dst = gwqh; off = i - CVT_N0; }
    else                           { s = wp; dst = gwph; off = i - CVT_N0 - CVT_N1; }
    float4 v = *(const float4*)(s + off);
    *(__half2*)(dst + off)     = __floats2half2_rn(v.x, v.y);
    *(__half2*)(dst + off + 2) = __floats2half2_rn(v.z, v.w);
}

// ---------------- helpers ----------------
__device__ __forceinline__ void mma4h(float* c, const uint32_t* a,
                                      uint32_t b0, uint32_t b1)
{
    asm volatile(
        "mma.sync.aligned.m16n8k16.row.col.f32.f16.f16.f32 "
        "{%0,%1,%2,%3}, {%4,%5,%6,%7}, {%8,%9}, {%0,%1,%2,%3};"
        : "+f"(c[0]), "+f"(c[1]), "+f"(c[2]), "+f"(c[3])
        : "r"(a[0]), "r"(a[1]), "r"(a[2]), "r"(a[3]), "r"(b0), "r"(b1));
}

__device__ __forceinline__ void ldsm4(uint32_t* r, const void* p)
{
    uint32_t a = (uint32_t)__cvta_generic_to_shared(p);
    asm volatile("ldmatrix.sync.aligned.m8n8.x4.shared.b16 {%0,%1,%2,%3}, [%4];"
                 : "=r"(r[0]), "=r"(r[1]), "=r"(r[2]), "=r"(r[3]) : "r"(a));
}

__device__ __forceinline__ uint32_t packh2(float v0, float v1)
{
    __half2 hp = __floats2half2_rn(v0, v1);
    return *(uint32_t*)&hp;
}

// L2-only (.cg) staging copies: streaming data, never re-read through L1.
__device__ __forceinline__ void cpa16(void* smem, const void* gmem)
{
    uint32_t s = (uint32_t)__cvta_generic_to_shared(smem);
    asm volatile("cp.async.cg.shared.global [%0], [%1], 16;"
                 :: "r"(s), "l"(gmem));
}
__device__ __forceinline__ void cpa_commit()
{ asm volatile("cp.async.commit_group;" ::: "memory"); }
template<int N>
__device__ __forceinline__ void cpa_wait()
{ asm volatile("cp.async.wait_group %0;" :: "n"(N) : "memory"); }

// ---------------------------------------------------------------------------
// HMMA GEMM — fp16 single-pass. 2-stage cp.async pipeline, K-chunk 64,
// 128x128 tile, ldmatrix. 8 warps = 4m x 2n; warp tile 32x64.  (R13 config)
// ---------------------------------------------------------------------------
#define GP 72                       // smem row stride (64 data + 8 pad)
#define NCHUNK 8
#define STAGE_E (2 * 128 * GP)
#define SMEM_BYTES (2 * STAGE_E * 2)   // 73728

template<int MODE>
__global__ __launch_bounds__(256, 2)
void hgemm_k(float* __restrict__ Cout)
{
    extern __shared__ __align__(16) __half smem[];

    const int tid = threadIdx.x;
    const int wid = tid >> 5, lane = tid & 31;
    const int g = lane >> 2, t = lane & 3;
    const int m0 = blockIdx.y << 7;
    const int n0 = blockIdx.x << 7;
    const int wm = (wid & 3) << 5;
    const int wn = (wid >> 2) << 6;

    const __half* asrc = (MODE == 0) ? gxh  : goh;
    const __half* bsrc = (MODE == 0) ? gwqh : gwph;

    const int a_r = (lane & 7) + ((lane >> 3) & 1) * 8;
    const int a_c = (lane >> 4) * 8;
    const int b_r = (lane & 7) + (lane >> 4) * 8;
    const int b_c = ((lane >> 3) & 1) * 8;

    auto As = [&](int s) { return smem + s * STAGE_E; };
    auto Bs = [&](int s) { return smem + s * STAGE_E + 128 * GP; };

    auto load_chunk = [&](int c, int s) {
        const int kc = c << 6;
        __half* as_ = As(s);
        __half* bs_ = Bs(s);
#pragma unroll
        for (int i = 0; i < 4; i++) {
            int idx = tid + (i << 8);
            int row = idx >> 3, cu = (idx & 7) << 3;
            cpa16(as_ + row * GP + cu,
                  asrc + (size_t)(m0 + row) * DIMC + kc + cu);
            cpa16(bs_ + row * GP + cu,
                  bsrc + (size_t)(n0 + row) * DIMC + kc + cu);
        }
        cpa_commit();
    };

    float acc[2][8][4];
#pragma unroll
    for (int mi = 0; mi < 2; mi++)
#pragma unroll
        for (int ni = 0; ni < 8; ni++)
#pragma unroll
            for (int c = 0; c < 4; c++) acc[mi][ni][c] = 0.f;

    load_chunk(0, 0);

    for (int c = 0; c < NCHUNK; c++) {
        const int s = c & 1;
        cpa_wait<0>();
        __syncthreads();
        if (c + 1 < NCHUNK) load_chunk(c + 1, s ^ 1);

        const __half* Ab = As(s);
        const __half* Bb = Bs(s);
#pragma unroll
        for (int ks = 0; ks < 4; ks++) {
            const int k0 = ks << 4;
            uint32_t af[2][4];
            ldsm4(af[0], Ab + (wm + a_r) * GP + k0 + a_c);
            ldsm4(af[1], Ab + (wm + 16 + a_r) * GP + k0 + a_c);
#pragma unroll
            for (int np = 0; np < 4; np++) {
                uint32_t bq[4];
                ldsm4(bq, Bb + (wn + np * 16 + b_r) * GP + k0 + b_c);
                mma4h(acc[0][np * 2],     af[0], bq[0], bq[1]);
                mma4h(acc[1][np * 2],     af[1], bq[0], bq[1]);
                mma4h(acc[0][np * 2 + 1], af[0], bq[2], bq[3]);
                mma4h(acc[1][np * 2 + 1], af[1], bq[2], bq[3]);
            }
        }
    }

    if (MODE == 0) {
#pragma unroll
        for (int mi = 0; mi < 2; mi++)
#pragma unroll
            for (int ni = 0; ni < 8; ni++) {
                int gm  = m0 + wm + (mi << 4) + g;
                int gm2 = gm + 8;
                int col = n0 + wn + (ni << 3) + 2 * t;
                int which = col >> 9;
                int h = (col >> 6) & (NHD - 1);
                int d = col & (HDD - 1);
                int b1_ = gm >> 10,  n1_ = gm & (NN - 1);
                int b2_ = gm2 >> 10, n2_ = gm2 & (NN - 1);
                if (which == 2) {
                    size_t vb1 = ((size_t)((b1_ * NHD + h) * HDD + d)) * NN + n1_;
                    gvth[vb1]      = __float2half_rn(acc[mi][ni][0]);
                    gvth[vb1 + NN] = __float2half_rn(acc[mi][ni][1]);
                    size_t vb2 = ((size_t)((b2_ * NHD + h) * HDD + d)) * NN + n2_;
                    gvth[vb2]      = __float2half_rn(acc[mi][ni][2]);
                    gvth[vb2 + NN] = __float2half_rn(acc[mi][ni][3]);
                } else {
                    __half* dst = which ? gkh : gqh;
                    size_t qb1 = ((size_t)((b1_ * NHD + h) * NN + n1_)) * HDD + d;
                    *(uint32_t*)(dst + qb1) = packh2(acc[mi][ni][0], acc[mi][ni][1]);
                    size_t qb2 = ((size_t)((b2_ * NHD + h) * NN + n2_)) * HDD + d;
                    *(uint32_t*)(dst + qb2) = packh2(acc[mi][ni][2], acc[mi][ni][3]);
                }
            }
    } else {
#pragma unroll
        for (int mi = 0; mi < 2; mi++)
#pragma unroll
            for (int ni = 0; ni < 8; ni++) {
                int gm = m0 + wm + (mi << 4) + g;
                int cc = n0 + wn + (ni << 3) + 2 * t;
                *(float2*)(Cout + (size_t)gm * DIMC + cc) =
                    make_float2(acc[mi][ni][0], acc[mi][ni][1]);
                *(float2*)(Cout + (size_t)(gm + 8) * DIMC + cc) =
                    make_float2(acc[mi][ni][2], acc[mi][ni][3]);
            }
    }
}

// ---------------------------------------------------------------------------
// Tensor-core flash attention — R13 config (2-stage, log2 softmax, bias
// fast path), validated at 143.7 us.
// ---------------------------------------------------------------------------
#define KPAD 72
#define TILE_E (64 * KPAD)
#define ASTAGE (2 * TILE_E)
#define ATTN_SMEM (2 * ASTAGE * 2) // 36864 bytes
#define LOG2E 1.4426950408889634f

__global__ __launch_bounds__(256, 2)
void attn_k(const float* __restrict__ logd, const int* __restrict__ pW)
{
    extern __shared__ __align__(16) __half asmem[];

    const int bh = blockIdx.y;
    const int b = bh >> 3, h = bh & 7;
    const int q0 = blockIdx.x << 7;
    const int tid = threadIdx.x;
    const int wid = tid >> 5, lane = tid & 31;
    const int g = lane >> 2, t = lane & 3;
    const int b_r = (lane & 7) + (lane >> 4) * 8;
    const int b_c = ((lane >> 3) & 1) * 8;

    const int Wg = pW ? *pW : 32;
    const float invW = 1.0f / (float)Wg;
    const float decay = log1pf(expf(logd[h]));
    const float scale2 = 0.125f * LOG2E;
    const float decay2 = decay * LOG2E;
    const bool fast = (Wg == 32);

    const size_t kbase = (size_t)bh * NN * HDD;

    auto Kh = [&](int s) { return asmem + s * ASTAGE; };
    auto Vh = [&](int s) { return asmem + s * ASTAGE + TILE_E; };

    auto load_tile = [&](int tk, int s) {
        const int k0 = tk << 6;
#pragma unroll
        for (int i = 0; i < 2; i++) {
            int idx = tid + (i << 8);
            int row = idx >> 3, cu = (idx & 7) << 3;
            cpa16(Kh(s) + row * KPAD + cu,
                  gkh + kbase + (size_t)(k0 + row) * HDD + cu);
            cpa16(Vh(s) + row * KPAD + cu,
                  gvth + kbase + (size_t)row * NN + k0 + cu);
        }
        cpa_commit();
    };

    const int qrow0 = q0 + (wid << 4) + g;
    const int qrow1 = qrow0 + 8;
    uint32_t qh[4][4];
#pragma unroll
    for (int kc = 0; kc < 4; kc++) {
        int c0 = kc * 16 + 2 * t;
        qh[kc][0] = *(const uint32_t*)(gqh + kbase + (size_t)qrow0 * HDD + c0);
        qh[kc][1] = *(const uint32_t*)(gqh + kbase + (size_t)qrow1 * HDD + c0);
        qh[kc][2] = *(const uint32_t*)(gqh + kbase + (size_t)qrow0 * HDD + c0 + 8);
        qh[kc][3] = *(const uint32_t*)(gqh + kbase + (size_t)qrow1 * HDD + c0 + 8);
    }

    int qri0 = (int)(((float)qrow0 + 0.5f) * invW);
    int qri1 = (int)(((float)qrow1 + 0.5f) * invW);
    const float qr0 = (float)qri0, qc0 = (float)(qrow0 - qri0 * Wg);
    const float qr1 = (float)qri1, qc1 = (float)(qrow1 - qri1 * Wg);

    float ccA0[4], ccB0[4], ccA1[4], ccB1[4];
    if (fast) {
#pragma unroll
        for (int j = 0; j < 4; j++) {
            float colA = (float)(j * 8 + 2 * t);
            float colB = colA + 1.f;
            ccA0[j] = -decay2 * fabsf(qc0 - colA);
            ccB0[j] = -decay2 * fabsf(qc0 - colB);
            ccA1[j] = -decay2 * fabsf(qc1 - colA);
            ccB1[j] = -decay2 * fabsf(qc1 - colB);
        }
    }

    float mg0 = -1e30f, lg0 = 0.f, mg1 = -1e30f, lg1 = 0.f;
    float accO[8][4];
#pragma unroll
    for (int ni = 0; ni < 8; ni++)
#pragma unroll
        for (int c = 0; c < 4; c++) accO[ni][c] = 0.f;

    load_tile(0, 0);

    for (int tk = 0; tk < 16; tk++) {
        const int s = tk & 1;
        const int k0 = tk << 6;
        cpa_wait<0>();
        __syncthreads();
        if (tk + 1 < 16) load_tile(tk + 1, s ^ 1);

        float S[8][4];
#pragma unroll
        for (int ni = 0; ni < 8; ni++)
#pragma unroll
            for (int c = 0; c < 4; c++) S[ni][c] = 0.f;

#pragma unroll
        for (int kc = 0; kc < 4; kc++) {
#pragma unroll
            for (int np = 0; np < 4; np++) {
                uint32_t bq[4];
                ldsm4(bq, Kh(s) + (np * 16 + b_r) * KPAD + kc * 16 + b_c);
                mma4h(S[np * 2],     qh[kc], bq[0], bq[1]);
                mma4h(S[np * 2 + 1], qh[kc], bq[2], bq[3]);
            }
        }

        if (fast) {
            float kr0 = (float)(2 * tk), kr1 = kr0 + 1.f;
            float r00 = -decay2 * fabsf(qr0 - kr0);
            float r01 = -decay2 * fabsf(qr0 - kr1);
            float r10 = -decay2 * fabsf(qr1 - kr0);
            float r11 = -decay2 * fabsf(qr1 - kr1);
#pragma unroll
            for (int ni = 0; ni < 8; ni++) {
                int j = ni & 3;
                float rq0 = (ni >> 2) ? r01 : r00;
                float rq1 = (ni >> 2) ? r11 : r10;
                S[ni][0] = fmaf(S[ni][0], scale2, rq0 + ccA0[j]);
                S[ni][1] = fmaf(S[ni][1], scale2, rq0 + ccB0[j]);
                S[ni][2] = fmaf(S[ni][2], scale2, rq1 + ccA1[j]);
                S[ni][3] = fmaf(S[ni][3], scale2, rq1 + ccB1[j]);
            }
        } else {
#pragma unroll
            for (int ni = 0; ni < 8; ni++) {
                int kA = k0 + ni * 8 + 2 * t;
                int kB = kA + 1;
                int krAi = (int)(((float)kA + 0.5f) * invW);
                int krBi = (int)(((float)kB + 0.5f) * invW);
                float krA = (float)krAi, kcA = (float)(kA - krAi * Wg);
                float krB = (float)krBi, kcB = (float)(kB - krBi * Wg);
                float dA0 = fabsf(qr0 - krA) + fabsf(qc0 - kcA);
                float dB0 = fabsf(qr0 - krB) + fabsf(qc0 - kcB);
                float dA1 = fabsf(qr1 - krA) + fabsf(qc1 - kcA);
                float dB1 = fabsf(qr1 - krB) + fabsf(qc1 - kcB);
                S[ni][0] = fmaf(S[ni][0], scale2, -decay2 * dA0);
                S[ni][1] = fmaf(S[ni][1], scale2, -decay2 * dB0);
                S[ni][2] = fmaf(S[ni][2], scale2, -decay2 * dA1);
                S[ni][3] = fmaf(S[ni][3], scale2, -decay2 * dB1);
            }
        }

        float mx0 = -1e30f, mx1 = -1e30f;
#pragma unroll
        for (int ni = 0; ni < 8; ni++) {
            mx0 = fmaxf(mx0, fmaxf(S[ni][0], S[ni][1]));
            mx1 = fmaxf(mx1, fmaxf(S[ni][2], S[ni][3]));
        }
        mx0 = fmaxf(mx0, __shfl_xor_sync(0xffffffffu, mx0, 1));
        mx0 = fmaxf(mx0, __shfl_xor_sync(0xffffffffu, mx0, 2));
        mx1 = fmaxf(mx1, __shfl_xor_sync(0xffffffffu, mx1, 1));
        mx1 = fmaxf(mx1, __shfl_xor_sync(0xffffffffu, mx1, 2));
        float nm0 = fmaxf(mg0, mx0), nm1 = fmaxf(mg1, mx1);
        float al0 = exp2f(mg0 - nm0), al1 = exp2f(mg1 - nm1);
        float sum0 = 0.f, sum1 = 0.f;
#pragma unroll
        for (int ni = 0; ni < 8; ni++) {
            S[ni][0] = exp2f(S[ni][0] - nm0); sum0 += S[ni][0];
            S[ni][1] = exp2f(S[ni][1] - nm0); sum0 += S[ni][1];
            S[ni][2] = exp2f(S[ni][2] - nm1); sum1 += S[ni][2];
            S[ni][3] = exp2f(S[ni][3] - nm1); sum1 += S[ni][3];
        }
        sum0 += __shfl_xor_sync(0xffffffffu, sum0, 1);
        sum0 += __shfl_xor_sync(0xffffffffu, sum0, 2);
        sum1 += __shfl_xor_sync(0xffffffffu, sum1, 1);
        sum1 += __shfl_xor_sync(0xffffffffu, sum1, 2);
        lg0 = lg0 * al0 + sum0;  mg0 = nm0;
        lg1 = lg1 * al1 + sum1;  mg1 = nm1;
#pragma unroll
        for (int ni = 0; ni < 8; ni++) {
            accO[ni][0] *= al0; accO[ni][1] *= al0;
            accO[ni][2] *= al1; accO[ni][3] *= al1;
        }

#pragma unroll
        for (int kc = 0; kc < 4; kc++) {
            const int nA = 2 * kc, nB = 2 * kc + 1;
            uint32_t ph[4];
            ph[0] = packh2(S[nA][0], S[nA][1]);
            ph[1] = packh2(S[nA][2], S[nA][3]);
            ph[2] = packh2(S[nB][0], S[nB][1]);
            ph[3] = packh2(S[nB][2], S[nB][3]);
#pragma unroll
            for (int np = 0; np < 4; np++) {
                uint32_t vq[4];
                ldsm4(vq, Vh(s) + (np * 16 + b_r) * KPAD + kc * 16 + b_c);
                mma4h(accO[np * 2],     ph, vq[0], vq[1]);
                mma4h(accO[np * 2 + 1], ph, vq[2], vq[3]);
            }
        }
    }

    const float inv0 = 1.f / lg0;
    const float inv1 = 1.f / lg1;
#pragma unroll
    for (int ni = 0; ni < 8; ni++) {
        int d = ni * 8 + 2 * t;
        size_t o0 = ((size_t)(b * NN + qrow0)) * DIMC + h * HDD + d;
        size_t o1 = ((size_t)(b * NN + qrow1)) * DIMC + h * HDD + d;
        *(uint32_t*)(goh + o0) = packh2(accO[ni][0] * inv0, accO[ni][1] * inv0);
        *(uint32_t*)(goh + o1) = packh2(accO[ni][2] * inv1, accO[ni][3] * inv1);
    }
}

// ---------------------------------------------------------------------------
extern "C" void kernel_launch(void* const* d_in, const int* in_sizes, int n_in,
                              void* d_out, int out_size)
{
    const float* x      = (const float*)d_in[0];
    const float* w_qkv  = (const float*)d_in[1];
    const float* w_proj = (const float*)d_in[2];
    const float* logd   = (const float*)d_in[3];
    const int*   pW     = (n_in > 5) ? (const int*)d_in[5] : nullptr;
    float* out = (float*)d_out;

    cudaFuncSetAttribute(hgemm_k<0>, cudaFuncAttributeMaxDynamicSharedMemorySize, SMEM_BYTES);
    cudaFuncSetAttribute(hgemm_k<1>, cudaFuncAttributeMaxDynamicSharedMemorySize, SMEM_BYTES);
    cudaFuncSetAttribute(attn_k, cudaFuncAttributeMaxDynamicSharedMemorySize, ATTN_SMEM);

    cvtall_k<<<(CVT_TOT / 4 + 255) / 256, 256>>>(x, w_qkv, w_proj);
    hgemm_k<0><<<dim3(12, 64), 256, SMEM_BYTES>>>(nullptr);
    attn_k<<<dim3(8, 64), 256, ATTN_SMEM>>>(logd, pW);
    hgemm_k<1><<<dim3(4, 64), 256, SMEM_BYTES>>>(out);
}

// round 17
// speedup vs baseline: 1.5503x; 1.5503x over previous
#include <cuda_runtime.h>
#include <cuda_bf16.h>
#include <cuda_fp16.h>
#include <cstdint>
#include <math.h>

#define DIMC 512
#define NHD  8
#define HDD  64
#define BB   8
#define NN   1024
#define MTOT (BB*NN)   // 8192
#define QKV  (BB*NHD*NN*HDD)

// ---------------- scratch (allocation-free) ----------------
__device__ __align__(16) __half gxh[MTOT*DIMC];        // x   fp16
__device__ __align__(16) __half gwqh[3*DIMC*DIMC];     // w_qkv fp16
__device__ __align__(16) __half gwph[DIMC*DIMC];       // w_proj fp16
__device__ __align__(16) __half gqh[QKV];              // [bh][n][d]
__device__ __align__(16) __half gkh[QKV];              // [bh][n][d]
__device__ __align__(16) __half gvth[QKV];             // [bh][d][n] (transposed)
__device__ __align__(16) __half goh[MTOT*DIMC];        // attn out [b][n][c]

// ---------------- fused fp32 -> fp16 convert (one launch) ----------------
#define CVT_N0 (MTOT*DIMC)
#define CVT_N1 (3*DIMC*DIMC)
#define CVT_N2 (DIMC*DIMC)
#define CVT_TOT (CVT_N0 + CVT_N1 + CVT_N2)

__global__ void cvtall_k(const float* __restrict__ x,
                         const float* __restrict__ wq,
                         const float* __restrict__ wp)
{
    int i = (blockIdx.x * blockDim.x + threadIdx.x) * 4;
    if (i >= CVT_TOT) return;
    const float* s;
    __half* dst;
    int off;
    if (i < CVT_N0)                { s = x;  dst = gxh;  off = i; }
    else if (i < CVT_N0 + CVT_N1)  { s = wq; dst = gwqh; off = i - CVT_N0; }
    else                           { s = wp; dst = gwph; off = i - CVT_N0 - CVT_N1; }
    float4 v = *(const float4*)(s + off);
    *(__half2*)(dst + off)     = __floats2half2_rn(v.x, v.y);
    *(__half2*)(dst + off + 2) = __floats2half2_rn(v.z, v.w);
}

// ---------------- helpers ----------------
__device__ __forceinline__ void mma4h(float* c, const uint32_t* a,
                                      uint32_t b0, uint32_t b1)
{
    asm volatile(
        "mma.sync.aligned.m16n8k16.row.col.f32.f16.f16.f32 "
        "{%0,%1,%2,%3}, {%4,%5,%6,%7}, {%8,%9}, {%0,%1,%2,%3};"
        : "+f"(c[0]), "+f"(c[1]), "+f"(c[2]), "+f"(c[3])
        : "r"(a[0]), "r"(a[1]), "r"(a[2]), "r"(a[3]), "r"(b0), "r"(b1));
}

__device__ __forceinline__ void ldsm4(uint32_t* r, const void* p)
{
    uint32_t a = (uint32_t)__cvta_generic_to_shared(p);
    asm volatile("ldmatrix.sync.aligned.m8n8.x4.shared.b16 {%0,%1,%2,%3}, [%4];"
                 : "=r"(r[0]), "=r"(r[1]), "=r"(r[2]), "=r"(r[3]) : "r"(a));
}

__device__ __forceinline__ uint32_t packh2(float v0, float v1)
{
    __half2 hp = __floats2half2_rn(v0, v1);
    return *(uint32_t*)&hp;
}

// .ca staging: A/W/K/V tiles have heavy inter-CTA reuse -> keep L1 fills.
__device__ __forceinline__ void cpa16(void* smem, const void* gmem)
{
    uint32_t s = (uint32_t)__cvta_generic_to_shared(smem);
    asm volatile("cp.async.ca.shared.global [%0], [%1], 16;"
                 :: "r"(s), "l"(gmem));
}
__device__ __forceinline__ void cpa_commit()
{ asm volatile("cp.async.commit_group;" ::: "memory"); }
template<int N>
__device__ __forceinline__ void cpa_wait()
{ asm volatile("cp.async.wait_group %0;" :: "n"(N) : "memory"); }

// ---------------------------------------------------------------------------
// HMMA GEMM — fp16 single-pass. 2-stage cp.async pipeline, K-chunk 64,
// 128x128 tile, ldmatrix. 8 warps = 4m x 2n; warp tile 32x64. (R13 best)
// ---------------------------------------------------------------------------
#define GP 72                       // smem row stride (64 data + 8 pad)
#define NCHUNK 8
#define STAGE_E (2 * 128 * GP)
#define SMEM_BYTES (2 * STAGE_E * 2)   // 73728

template<int MODE>
__global__ __launch_bounds__(256, 2)
void hgemm_k(float* __restrict__ Cout)
{
    extern __shared__ __align__(16) __half smem[];

    const int tid = threadIdx.x;
    const int wid = tid >> 5, lane = tid & 31;
    const int g = lane >> 2, t = lane & 3;
    const int m0 = blockIdx.y << 7;
    const int n0 = blockIdx.x << 7;
    const int wm = (wid & 3) << 5;
    const int wn = (wid >> 2) << 6;

    const __half* asrc = (MODE == 0) ? gxh  : goh;
    const __half* bsrc = (MODE == 0) ? gwqh : gwph;

    const int a_r = (lane & 7) + ((lane >> 3) & 1) * 8;
    const int a_c = (lane >> 4) * 8;
    const int b_r = (lane & 7) + (lane >> 4) * 8;
    const int b_c = ((lane >> 3) & 1) * 8;

    auto As = [&](int s) { return smem + s * STAGE_E; };
    auto Bs = [&](int s) { return smem + s * STAGE_E + 128 * GP; };

    auto load_chunk = [&](int c, int s) {
        const int kc = c << 6;
        __half* as_ = As(s);
        __half* bs_ = Bs(s);
#pragma unroll
        for (int i = 0; i < 4; i++) {
            int idx = tid + (i << 8);
            int row = idx >> 3, cu = (idx & 7) << 3;
            cpa16(as_ + row * GP + cu,
                  asrc + (size_t)(m0 + row) * DIMC + kc + cu);
            cpa16(bs_ + row * GP + cu,
                  bsrc + (size_t)(n0 + row) * DIMC + kc + cu);
        }
        cpa_commit();
    };

    float acc[2][8][4];
#pragma unroll
    for (int mi = 0; mi < 2; mi++)
#pragma unroll
        for (int ni = 0; ni < 8; ni++)
#pragma unroll
            for (int c = 0; c < 4; c++) acc[mi][ni][c] = 0.f;

    load_chunk(0, 0);

    for (int c = 0; c < NCHUNK; c++) {
        const int s = c & 1;
        cpa_wait<0>();
        __syncthreads();
        if (c + 1 < NCHUNK) load_chunk(c + 1, s ^ 1);

        const __half* Ab = As(s);
        const __half* Bb = Bs(s);
#pragma unroll
        for (int ks = 0; ks < 4; ks++) {
            const int k0 = ks << 4;
            uint32_t af[2][4];
            ldsm4(af[0], Ab + (wm + a_r) * GP + k0 + a_c);
            ldsm4(af[1], Ab + (wm + 16 + a_r) * GP + k0 + a_c);
#pragma unroll
            for (int np = 0; np < 4; np++) {
                uint32_t bq[4];
                ldsm4(bq, Bb + (wn + np * 16 + b_r) * GP + k0 + b_c);
                mma4h(acc[0][np * 2],     af[0], bq[0], bq[1]);
                mma4h(acc[1][np * 2],     af[1], bq[0], bq[1]);
                mma4h(acc[0][np * 2 + 1], af[0], bq[2], bq[3]);
                mma4h(acc[1][np * 2 + 1], af[1], bq[2], bq[3]);
            }
        }
    }

    if (MODE == 0) {
#pragma unroll
        for (int mi = 0; mi < 2; mi++)
#pragma unroll
            for (int ni = 0; ni < 8; ni++) {
                int gm  = m0 + wm + (mi << 4) + g;
                int gm2 = gm + 8;
                int col = n0 + wn + (ni << 3) + 2 * t;
                int which = col >> 9;
                int h = (col >> 6) & (NHD - 1);
                int d = col & (HDD - 1);
                int b1_ = gm >> 10,  n1_ = gm & (NN - 1);
                int b2_ = gm2 >> 10, n2_ = gm2 & (NN - 1);
                if (which == 2) {
                    size_t vb1 = ((size_t)((b1_ * NHD + h) * HDD + d)) * NN + n1_;
                    gvth[vb1]      = __float2half_rn(acc[mi][ni][0]);
                    gvth[vb1 + NN] = __float2half_rn(acc[mi][ni][1]);
                    size_t vb2 = ((size_t)((b2_ * NHD + h) * HDD + d)) * NN + n2_;
                    gvth[vb2]      = __float2half_rn(acc[mi][ni][2]);
                    gvth[vb2 + NN] = __float2half_rn(acc[mi][ni][3]);
                } else {
                    __half* dst = which ? gkh : gqh;
                    size_t qb1 = ((size_t)((b1_ * NHD + h) * NN + n1_)) * HDD + d;
                    *(uint32_t*)(dst + qb1) = packh2(acc[mi][ni][0], acc[mi][ni][1]);
                    size_t qb2 = ((size_t)((b2_ * NHD + h) * NN + n2_)) * HDD + d;
                    *(uint32_t*)(dst + qb2) = packh2(acc[mi][ni][2], acc[mi][ni][3]);
                }
            }
    } else {
#pragma unroll
        for (int mi = 0; mi < 2; mi++)
#pragma unroll
            for (int ni = 0; ni < 8; ni++) {
                int gm = m0 + wm + (mi << 4) + g;
                int cc = n0 + wn + (ni << 3) + 2 * t;
                *(float2*)(Cout + (size_t)gm * DIMC + cc) =
                    make_float2(acc[mi][ni][0], acc[mi][ni][1]);
                *(float2*)(Cout + (size_t)(gm + 8) * DIMC + cc) =
                    make_float2(acc[mi][ni][2], acc[mi][ni][3]);
            }
    }
}

// ---------------------------------------------------------------------------
// Tensor-core flash attention — R13 best config (2-stage cp.async, ldmatrix,
// log2-domain softmax, Wg==32 bias fast path).
// ---------------------------------------------------------------------------
#define KPAD 72
#define TILE_E (64 * KPAD)
#define ASTAGE (2 * TILE_E)
#define ATTN_SMEM (2 * ASTAGE * 2) // 36864 bytes
#define LOG2E 1.4426950408889634f

__global__ __launch_bounds__(256, 2)
void attn_k(const float* __restrict__ logd, const int* __restrict__ pW)
{
    extern __shared__ __align__(16) __half asmem[];

    const int bh = blockIdx.y;
    const int b = bh >> 3, h = bh & 7;
    const int q0 = blockIdx.x << 7;
    const int tid = threadIdx.x;
    const int wid = tid >> 5, lane = tid & 31;
    const int g = lane >> 2, t = lane & 3;
    const int b_r = (lane & 7) + (lane >> 4) * 8;
    const int b_c = ((lane >> 3) & 1) * 8;

    const int Wg = pW ? *pW : 32;
    const float invW = 1.0f / (float)Wg;
    const float decay = log1pf(expf(logd[h]));
    const float scale2 = 0.125f * LOG2E;
    const float decay2 = decay * LOG2E;
    const bool fast = (Wg == 32);

    const size_t kbase = (size_t)bh * NN * HDD;

    auto Kh = [&](int s) { return asmem + s * ASTAGE; };
    auto Vh = [&](int s) { return asmem + s * ASTAGE + TILE_E; };

    auto load_tile = [&](int tk, int s) {
        const int k0 = tk << 6;
#pragma unroll
        for (int i = 0; i < 2; i++) {
            int idx = tid + (i << 8);
            int row = idx >> 3, cu = (idx & 7) << 3;
            cpa16(Kh(s) + row * KPAD + cu,
                  gkh + kbase + (size_t)(k0 + row) * HDD + cu);
            cpa16(Vh(s) + row * KPAD + cu,
                  gvth + kbase + (size_t)row * NN + k0 + cu);
        }
        cpa_commit();
    };

    const int qrow0 = q0 + (wid << 4) + g;
    const int qrow1 = qrow0 + 8;
    uint32_t qh[4][4];
#pragma unroll
    for (int kc = 0; kc < 4; kc++) {
        int c0 = kc * 16 + 2 * t;
        qh[kc][0] = *(const uint32_t*)(gqh + kbase + (size_t)qrow0 * HDD + c0);
        qh[kc][1] = *(const uint32_t*)(gqh + kbase + (size_t)qrow1 * HDD + c0);
        qh[kc][2] = *(const uint32_t*)(gqh + kbase + (size_t)qrow0 * HDD + c0 + 8);
        qh[kc][3] = *(const uint32_t*)(gqh + kbase + (size_t)qrow1 * HDD + c0 + 8);
    }

    int qri0 = (int)(((float)qrow0 + 0.5f) * invW);
    int qri1 = (int)(((float)qrow1 + 0.5f) * invW);
    const float qr0 = (float)qri0, qc0 = (float)(qrow0 - qri0 * Wg);
    const float qr1 = (float)qri1, qc1 = (float)(qrow1 - qri1 * Wg);

    float ccA0[4], ccB0[4], ccA1[4], ccB1[4];
    if (fast) {
#pragma unroll
        for (int j = 0; j < 4; j++) {
            float colA = (float)(j * 8 + 2 * t);
            float colB = colA + 1.f;
            ccA0[j] = -decay2 * fabsf(qc0 - colA);
            ccB0[j] = -decay2 * fabsf(qc0 - colB);
            ccA1[j] = -decay2 * fabsf(qc1 - colA);
            ccB1[j] = -decay2 * fabsf(qc1 - colB);
        }
    }

    float mg0 = -1e30f, lg0 = 0.f, mg1 = -1e30f, lg1 = 0.f;
    float accO[8][4];
#pragma unroll
    for (int ni = 0; ni < 8; ni++)
#pragma unroll
        for (int c = 0; c < 4; c++) accO[ni][c] = 0.f;

    load_tile(0, 0);

    for (int tk = 0; tk < 16; tk++) {
        const int s = tk & 1;
        const int k0 = tk << 6;
        cpa_wait<0>();
        __syncthreads();
        if (tk + 1 < 16) load_tile(tk + 1, s ^ 1);

        float S[8][4];
#pragma unroll
        for (int ni = 0; ni < 8; ni++)
#pragma unroll
            for (int c = 0; c < 4; c++) S[ni][c] = 0.f;

#pragma unroll
        for (int kc = 0; kc < 4; kc++) {
#pragma unroll
            for (int np = 0; np < 4; np++) {
                uint32_t bq[4];
                ldsm4(bq, Kh(s) + (np * 16 + b_r) * KPAD + kc * 16 + b_c);
                mma4h(S[np * 2],     qh[kc], bq[0], bq[1]);
                mma4h(S[np * 2 + 1], qh[kc], bq[2], bq[3]);
            }
        }

        if (fast) {
            float kr0 = (float)(2 * tk), kr1 = kr0 + 1.f;
            float r00 = -decay2 * fabsf(qr0 - kr0);
            float r01 = -decay2 * fabsf(qr0 - kr1);
            float r10 = -decay2 * fabsf(qr1 - kr0);
            float r11 = -decay2 * fabsf(qr1 - kr1);
#pragma unroll
            for (int ni = 0; ni < 8; ni++) {
                int j = ni & 3;
                float rq0 = (ni >> 2) ? r01 : r00;
                float rq1 = (ni >> 2) ? r11 : r10;
                S[ni][0] = fmaf(S[ni][0], scale2, rq0 + ccA0[j]);
                S[ni][1] = fmaf(S[ni][1], scale2, rq0 + ccB0[j]);
                S[ni][2] = fmaf(S[ni][2], scale2, rq1 + ccA1[j]);
                S[ni][3] = fmaf(S[ni][3], scale2, rq1 + ccB1[j]);
            }
        } else {
#pragma unroll
            for (int ni = 0; ni < 8; ni++) {
                int kA = k0 + ni * 8 + 2 * t;
                int kB = kA + 1;
                int krAi = (int)(((float)kA + 0.5f) * invW);
                int krBi = (int)(((float)kB + 0.5f) * invW);
                float krA = (float)krAi, kcA = (float)(kA - krAi * Wg);
                float krB = (float)krBi, kcB = (float)(kB - krBi * Wg);
                float dA0 = fabsf(qr0 - krA) + fabsf(qc0 - kcA);
                float dB0 = fabsf(qr0 - krB) + fabsf(qc0 - kcB);
                float dA1 = fabsf(qr1 - krA) + fabsf(qc1 - kcA);
                float dB1 = fabsf(qr1 - krB) + fabsf(qc1 - kcB);
                S[ni][0] = fmaf(S[ni][0], scale2, -decay2 * dA0);
                S[ni][1] = fmaf(S[ni][1], scale2, -decay2 * dB0);
                S[ni][2] = fmaf(S[ni][2], scale2, -decay2 * dA1);
                S[ni][3] = fmaf(S[ni][3], scale2, -decay2 * dB1);
            }
        }

        float mx0 = -1e30f, mx1 = -1e30f;
#pragma unroll
        for (int ni = 0; ni < 8; ni++) {
            mx0 = fmaxf(mx0, fmaxf(S[ni][0], S[ni][1]));
            mx1 = fmaxf(mx1, fmaxf(S[ni][2], S[ni][3]));
        }
        mx0 = fmaxf(mx0, __shfl_xor_sync(0xffffffffu, mx0, 1));
        mx0 = fmaxf(mx0, __shfl_xor_sync(0xffffffffu, mx0, 2));
        mx1 = fmaxf(mx1, __shfl_xor_sync(0xffffffffu, mx1, 1));
        mx1 = fmaxf(mx1, __shfl_xor_sync(0xffffffffu, mx1, 2));
        float nm0 = fmaxf(mg0, mx0), nm1 = fmaxf(mg1, mx1);
        float al0 = exp2f(mg0 - nm0), al1 = exp2f(mg1 - nm1);
        float sum0 = 0.f, sum1 = 0.f;
#pragma unroll
        for (int ni = 0; ni < 8; ni++) {
            S[ni][0] = exp2f(S[ni][0] - nm0); sum0 += S[ni][0];
            S[ni][1] = exp2f(S[ni][1] - nm0); sum0 += S[ni][1];
            S[ni][2] = exp2f(S[ni][2] - nm1); sum1 += S[ni][2];
            S[ni][3] = exp2f(S[ni][3] - nm1); sum1 += S[ni][3];
        }
        sum0 += __shfl_xor_sync(0xffffffffu, sum0, 1);
        sum0 += __shfl_xor_sync(0xffffffffu, sum0, 2);
        sum1 += __shfl_xor_sync(0xffffffffu, sum1, 1);
        sum1 += __shfl_xor_sync(0xffffffffu, sum1, 2);
        lg0 = lg0 * al0 + sum0;  mg0 = nm0;
        lg1 = lg1 * al1 + sum1;  mg1 = nm1;
#pragma unroll
        for (int ni = 0; ni < 8; ni++) {
            accO[ni][0] *= al0; accO[ni][1] *= al0;
            accO[ni][2] *= al1; accO[ni][3] *= al1;
        }

#pragma unroll
        for (int kc = 0; kc < 4; kc++) {
            const int nA = 2 * kc, nB = 2 * kc + 1;
            uint32_t ph[4];
            ph[0] = packh2(S[nA][0], S[nA][1]);
            ph[1] = packh2(S[nA][2], S[nA][3]);
            ph[2] = packh2(S[nB][0], S[nB][1]);
            ph[3] = packh2(S[nB][2], S[nB][3]);
#pragma unroll
            for (int np = 0; np < 4; np++) {
                uint32_t vq[4];
                ldsm4(vq, Vh(s) + (np * 16 + b_r) * KPAD + kc * 16 + b_c);
                mma4h(accO[np * 2],     ph, vq[0], vq[1]);
                mma4h(accO[np * 2 + 1], ph, vq[2], vq[3]);
            }
        }
    }

    const float inv0 = 1.f / lg0;
    const float inv1 = 1.f / lg1;
#pragma unroll
    for (int ni = 0; ni < 8; ni++) {
        int d = ni * 8 + 2 * t;
        size_t o0 = ((size_t)(b * NN + qrow0)) * DIMC + h * HDD + d;
        size_t o1 = ((size_t)(b * NN + qrow1)) * DIMC + h * HDD + d;
        *(uint32_t*)(goh + o0) = packh2(accO[ni][0] * inv0, accO[ni][1] * inv0);
        *(uint32_t*)(goh + o1) = packh2(accO[ni][2] * inv1, accO[ni][3] * inv1);
    }
}

// ---------------------------------------------------------------------------
extern "C" void kernel_launch(void* const* d_in, const int* in_sizes, int n_in,
                              void* d_out, int out_size)
{
    const float* x      = (const float*)d_in[0];
    const float* w_qkv  = (const float*)d_in[1];
    const float* w_proj = (const float*)d_in[2];
    const float* logd   = (const float*)d_in[3];
    const int*   pW     = (n_in > 5) ? (const int*)d_in[5] : nullptr;
    float* out = (float*)d_out;

    cudaFuncSetAttribute(hgemm_k<0>, cudaFuncAttributeMaxDynamicSharedMemorySize, SMEM_BYTES);
    cudaFuncSetAttribute(hgemm_k<1>, cudaFuncAttributeMaxDynamicSharedMemorySize, SMEM_BYTES);
    cudaFuncSetAttribute(attn_k, cudaFuncAttributeMaxDynamicSharedMemorySize, ATTN_SMEM);

    cvtall_k<<<(CVT_TOT / 4 + 255) / 256, 256>>>(x, w_qkv, w_proj);
    hgemm_k<0><<<dim3(12, 64), 256, SMEM_BYTES>>>(nullptr);
    attn_k<<<dim3(8, 64), 256, ATTN_SMEM>>>(logd, pW);
    hgemm_k<1><<<dim3(4, 64), 256, SMEM_BYTES>>>(out);
}